// round 14
// baseline (speedup 1.0000x reference)
#include <cuda_runtime.h>
#include <cuda_fp16.h>
#include <math.h>
#include <math_constants.h>
#include <stdint.h>

// ============================================================================
// StressNNEval — round 14: 32-row tiles, 3 CTAs/SM (6 warps/SMSP).
//   fp16 split; L1 3-term, L2..L4 2-term; ping-pong hi-act buffers;
//   serialized wfh->wfl loads keep live regs ~76 (fits 84-reg cap).
//   Arithmetic identical to round 13.
// ============================================================================

#define MAXB 262144
#define HID  256

__device__ __align__(128) float    g_b1p[HID];
__device__ __align__(128) uint32_t g_f1[16384];        // L1 frags (hi+lo fp16)
__device__ __align__(128) uint32_t g_fN[3 * 65536];    // L2..L4 frags (hi+lo fp16)

// ---- smem layout (dynamic, 44224 B; 3 CTAs/SM) -----------------------------
#define ACT0     0              // 32 rows x 528B (hi acts, ping; L4 hi at end)
#define ACT1     16896          // 32 rows x 528B (hi acts, pong)
#define RBUF     33792          // 32 x 9 fp32                  [persistent]
#define X0LO     34944          // 32 rows x 80B (X0 lo)        [dead after L1]
#define BIASALL  37504          // 4 x 256 fp32 (b1p,b2,b3,b4)  [dead after L4]
#define W5S      34944          // overlay: 256x9 fp32          [after mainloop]
#define B5S      44160          // 9 fp32
#define SMEM_TOT 44224

// ---------------------------------------------------------------------------
__device__ __forceinline__ uint32_t smem_u32(const void* p) {
    uint32_t a;
    asm("{ .reg .u64 t; cvta.to.shared.u64 t, %1; cvt.u32.u64 %0, t; }"
        : "=r"(a) : "l"(p));
    return a;
}
#define LDSM4(r, addr)                                                        \
    asm volatile("ldmatrix.sync.aligned.m8n8.x4.shared.b16 {%0,%1,%2,%3}, [%4];" \
        : "=r"((r)[0]), "=r"((r)[1]), "=r"((r)[2]), "=r"((r)[3]) : "r"(addr))

#define MMA_FP16(c, a, b0, b1)                                                \
    asm volatile("mma.sync.aligned.m16n8k16.row.col.f32.f16.f16.f32 "         \
        "{%0,%1,%2,%3}, {%4,%5,%6,%7}, {%8,%9}, {%0,%1,%2,%3};"               \
        : "+f"((c)[0]), "+f"((c)[1]), "+f"((c)[2]), "+f"((c)[3])              \
        : "r"((a)[0]), "r"((a)[1]), "r"((a)[2]), "r"((a)[3]),                 \
          "r"(b0), "r"(b1))

__device__ __forceinline__ float gelu_f(float t) {
    return 0.5f * t * (1.0f + erff(t * 0.7071067811865475f));
}

// ---------------------------------------------------------------------------
// prep: block 0 folds latent into b1; blocks 1..64: L1 frags;
//       blocks 65..832: L2..L4 frags.  (fragment layout as rounds 7-13)
// ---------------------------------------------------------------------------
__global__ void prep_all_kernel(const float* __restrict__ emb,
                                const int* __restrict__ traj,
                                const float* __restrict__ W1,
                                const float* __restrict__ b1,
                                const float* __restrict__ W2,
                                const float* __restrict__ W3,
                                const float* __restrict__ W4) {
    int bid = blockIdx.x, tid = threadIdx.x;
    if (bid == 0) {
        int t = traj[0];
        const float* e = emb + (size_t)t * 128;
        float s = b1[tid];
#pragma unroll 4
        for (int k = 0; k < 128; ++k)
            s += e[k] * W1[(size_t)(25 + k) * HID + tid];
        g_b1p[tid] = s;
        return;
    }
    bool isL1 = (bid <= 64);
    int idx = isL1 ? (bid - 1) * 256 + tid : 0;
    int L = 0;
    if (!isL1) {
        int q = (bid - 65) * 256 + tid;
        L = q >> 16;
        idx = q & 65535;
    }
    int lane4 = idx & 3;
    int lane  = (idx >> 2) & 31;
    int g     = (idx >> 7) & 7;
    int warp  = (idx >> 10) & 7;
    int c     = isL1 ? 0 : ((idx >> 13) & 7);
    int half  = g >> 2;
    int ks    = (g >> 1) & 1;
    int npair = g & 1;
    int n8    = npair * 2 + (lane4 >> 1);
    int r     = lane4 & 1;
    int n = warp * 32 + n8 * 8 + (lane >> 2);
    int k = c * 32 + ks * 16 + (lane & 3) * 2 + r * 8;

    float w0, w1;
    if (isL1) {
        w0 = (k < 25)     ? W1[(size_t)k * HID + n]       : 0.0f;
        w1 = (k + 1 < 25) ? W1[(size_t)(k + 1) * HID + n] : 0.0f;
    } else {
        const float* W = (L == 0) ? W2 : ((L == 1) ? W3 : W4);
        w0 = W[(size_t)k * HID + n];
        w1 = W[(size_t)(k + 1) * HID + n];
    }
    __half h0 = __float2half_rn(w0);
    __half h1 = __float2half_rn(w1);
    uint32_t val;
    if (half == 0) {
        val = (uint32_t)*reinterpret_cast<uint16_t*>(&h0) |
              ((uint32_t)*reinterpret_cast<uint16_t*>(&h1) << 16);
    } else {
        __half l0 = __float2half_rn(w0 - __half2float(h0));
        __half l1 = __float2half_rn(w1 - __half2float(h1));
        val = (uint32_t)*reinterpret_cast<uint16_t*>(&l0) |
              ((uint32_t)*reinterpret_cast<uint16_t*>(&l1) << 16);
    }
    if (isL1) g_f1[idx] = val;
    else      g_fN[(size_t)L * 65536 + idx] = val;
}

// ---------------------------------------------------------------------------
// Fused kernel: one CTA per 32-row tile, 256 threads, warp tile 32M x 32N.
// ---------------------------------------------------------------------------
__global__ __launch_bounds__(256, 3)
void fused_kernel(const float* __restrict__ F, const float* __restrict__ C,
                  const float* __restrict__ b2, const float* __restrict__ b3,
                  const float* __restrict__ b4, const float* __restrict__ W5,
                  const float* __restrict__ b5, float* __restrict__ out) {
    extern __shared__ char smem[];
    const uint32_t sb = smem_u32(smem);
    const int tid = threadIdx.x, lane = tid & 31, warp = tid >> 5;
    const int tile = blockIdx.x;

    // stage ALL biases once (read-only afterwards)
    {
        float* ba = reinterpret_cast<float*>(smem + BIASALL);
        ba[tid]       = g_b1p[tid];
        ba[256 + tid] = b2[tid];
        ba[512 + tid] = b3[tid];
        ba[768 + tid] = b4[tid];
    }

    // --- in-kernel prep: invariants + polar rotation -> X0 (hi->ACT0,
    //     lo->X0LO), R -> RBUF
    if (tid < 32) {
        int p = tile * 32 + tid;
        float Fm[3][3];
#pragma unroll
        for (int i = 0; i < 3; ++i)
#pragma unroll
            for (int j = 0; j < 3; ++j)
                Fm[i][j] = F[(size_t)p * 9 + i * 3 + j];

        float G[3][3];
#pragma unroll
        for (int i = 0; i < 3; ++i)
#pragma unroll
            for (int j = 0; j < 3; ++j)
                G[i][j] = Fm[0][i] * Fm[0][j] + Fm[1][i] * Fm[1][j] + Fm[2][i] * Fm[2][j];

        float q = (G[0][0] + G[1][1] + G[2][2]) * (1.0f / 3.0f);
        float p1 = G[0][1] * G[0][1] + G[0][2] * G[0][2] + G[1][2] * G[1][2];
        float p2 = (G[0][0] - q) * (G[0][0] - q) + (G[1][1] - q) * (G[1][1] - q) +
                   (G[2][2] - q) * (G[2][2] - q) + 2.0f * p1;
        float e1, e2, e3;
        float pp = sqrtf(p2 * (1.0f / 6.0f));
        if (pp < 1e-20f) {
            e1 = e2 = e3 = q;
        } else {
            float ip = 1.0f / pp;
            float b00 = (G[0][0] - q) * ip, b11 = (G[1][1] - q) * ip, b22 = (G[2][2] - q) * ip;
            float b01 = G[0][1] * ip, b02 = G[0][2] * ip, b12 = G[1][2] * ip;
            float detB = b00 * (b11 * b22 - b12 * b12) - b01 * (b01 * b22 - b12 * b02) +
                         b02 * (b01 * b12 - b11 * b02);
            float r = fminf(1.0f, fmaxf(-1.0f, detB * 0.5f));
            float phi = acosf(r) * (1.0f / 3.0f);
            e1 = q + 2.0f * pp * cosf(phi);
            e3 = q + 2.0f * pp * cosf(phi + 2.0943951023931953f);
            e2 = 3.0f * q - e1 - e3;
        }
        float s1 = sqrtf(fmaxf(e1, 0.0f));
        float s2 = sqrtf(fmaxf(e2, 0.0f));
        float s3 = sqrtf(fmaxf(e3, 0.0f));

        float detF = Fm[0][0] * (Fm[1][1] * Fm[2][2] - Fm[1][2] * Fm[2][1]) -
                     Fm[0][1] * (Fm[1][0] * Fm[2][2] - Fm[1][2] * Fm[2][0]) +
                     Fm[0][2] * (Fm[1][0] * Fm[2][1] - Fm[1][1] * Fm[2][0]);

        float X[3][3];
#pragma unroll
        for (int i = 0; i < 3; ++i)
#pragma unroll
            for (int j = 0; j < 3; ++j) X[i][j] = Fm[i][j];
#pragma unroll
        for (int it = 0; it < 8; ++it) {
            float c00 = X[1][1] * X[2][2] - X[1][2] * X[2][1];
            float c01 = X[1][2] * X[2][0] - X[1][0] * X[2][2];
            float c02 = X[1][0] * X[2][1] - X[1][1] * X[2][0];
            float c10 = X[0][2] * X[2][1] - X[0][1] * X[2][2];
            float c11 = X[0][0] * X[2][2] - X[0][2] * X[2][0];
            float c12 = X[0][1] * X[2][0] - X[0][0] * X[2][1];
            float c20 = X[0][1] * X[1][2] - X[0][2] * X[1][1];
            float c21 = X[0][2] * X[1][0] - X[0][0] * X[1][2];
            float c22 = X[0][0] * X[1][1] - X[0][1] * X[1][0];
            float d = X[0][0] * c00 + X[0][1] * c01 + X[0][2] * c02;
            float id = 0.5f / d;
            X[0][0] = 0.5f * X[0][0] + id * c00;  X[0][1] = 0.5f * X[0][1] + id * c01;
            X[0][2] = 0.5f * X[0][2] + id * c02;  X[1][0] = 0.5f * X[1][0] + id * c10;
            X[1][1] = 0.5f * X[1][1] + id * c11;  X[1][2] = 0.5f * X[1][2] + id * c12;
            X[2][0] = 0.5f * X[2][0] + id * c20;  X[2][1] = 0.5f * X[2][1] + id * c21;
            X[2][2] = 0.5f * X[2][2] + id * c22;
        }
#pragma unroll
        for (int i = 0; i < 9; ++i)
            reinterpret_cast<float*>(smem + RBUF)[tid * 9 + i] = X[i / 3][i % 3];

        float x0[32];
        x0[0] = s1 - 1.0f;  x0[1] = s2 - 1.0f;  x0[2] = s3 - 1.0f;
#pragma unroll
        for (int i = 0; i < 3; ++i)
#pragma unroll
            for (int j = 0; j < 3; ++j)
                x0[3 + i * 3 + j] = G[i][j] - ((i == j) ? 1.0f : 0.0f);
        x0[12] = detF - 1.0f;
        x0[13] = logf(detF) - 1.0f;
        float f00 = fmaxf(Fm[0][0], 1e-6f);
        x0[14] = f00 - 1.0f;
        x0[15] = logf(f00) - 1.0f;
#pragma unroll
        for (int k = 0; k < 9; ++k) x0[16 + k] = C[(size_t)p * 9 + k];
#pragma unroll
        for (int k = 25; k < 32; ++k) x0[k] = 0.0f;

#pragma unroll
        for (int cp = 0; cp < 16; ++cp) {
            float v0 = x0[2 * cp], v1 = x0[2 * cp + 1];
            __half2 h = __floats2half2_rn(v0, v1);
            float l0 = v0 - __half2float(__low2half(h));
            float l1 = v1 - __half2float(__high2half(h));
            __half2 lo = __floats2half2_rn(l0, l1);
            *reinterpret_cast<uint32_t*>(smem + ACT0 + tid * 528 + cp * 4) =
                *reinterpret_cast<uint32_t*>(&h);
            *reinterpret_cast<uint32_t*>(smem + X0LO + tid * 80 + cp * 4) =
                *reinterpret_cast<uint32_t*>(&lo);
        }
    }
    __syncthreads();

    // --- mainloop over layers; chunks inside; ping-pong act buffers --------
    float acc[2][4][4];
#pragma unroll
    for (int mt = 0; mt < 2; ++mt)
#pragma unroll
        for (int n8 = 0; n8 < 4; ++n8)
#pragma unroll
            for (int r = 0; r < 4; ++r) acc[mt][n8][r] = 0.0f;

    const uint32_t a_off    = (uint32_t)(lane & 15) * 528u + ((lane >> 4) << 4);
    const uint32_t a_off_lo = (uint32_t)(lane & 15) * 80u  + ((lane >> 4) << 4);
    const int r_l = lane >> 2, c_l = (lane & 3) << 1;

#pragma unroll 1
    for (int l = 0; l < 4; ++l) {
        const int nch = (l == 0) ? 1 : 8;
        const uint32_t rd = sb + ((l & 1) ? ACT1 : ACT0);   // LDSM only
        char* wrp = smem + ((l & 1) ? ACT0 : ACT1);         // l=3 -> ACT0
        const uint4* wbase = (l == 0)
            ? reinterpret_cast<const uint4*>(g_f1)
            : reinterpret_cast<const uint4*>(g_fN + (size_t)(l - 1) * 65536);
        const float* bias = reinterpret_cast<const float*>(smem + BIASALL) + l * 256;

#pragma unroll 1
        for (int ch = 0; ch < nch; ++ch) {
            const int fb = ((ch * 8 + warp) * 8) * 32 + lane;
            const uint32_t acol = (uint32_t)ch * 64u;

            // A-fragments for both ks, both mt: 16 regs, live across passes
            uint32_t ah[2][2][4];            // [ks][mt][4]
#pragma unroll
            for (int ks = 0; ks < 2; ++ks)
#pragma unroll
                for (int mt = 0; mt < 2; ++mt)
                    LDSM4(ah[ks][mt], rd + a_off + mt * 8448 + acol + ks * 32);

            // pass 1: hi weights
            uint4 wf[4];
#pragma unroll
            for (int g = 0; g < 4; ++g) wf[g] = __ldg(wbase + fb + g * 32);
#pragma unroll
            for (int ks = 0; ks < 2; ++ks) {
                uint32_t bh[4][2];
                uint4 q0 = wf[ks * 2], q1 = wf[ks * 2 + 1];
                bh[0][0] = q0.x; bh[0][1] = q0.y; bh[1][0] = q0.z; bh[1][1] = q0.w;
                bh[2][0] = q1.x; bh[2][1] = q1.y; bh[3][0] = q1.z; bh[3][1] = q1.w;
#pragma unroll
                for (int mt = 0; mt < 2; ++mt)
#pragma unroll
                    for (int n8 = 0; n8 < 4; ++n8)
                        MMA_FP16(acc[mt][n8], ah[ks][mt], bh[n8][0], bh[n8][1]);
                if (l == 0) {
#pragma unroll
                    for (int mt = 0; mt < 2; ++mt) {
                        uint32_t al[4];
                        LDSM4(al, sb + X0LO + a_off_lo + mt * 1280 + ks * 32);
#pragma unroll
                        for (int n8 = 0; n8 < 4; ++n8)
                            MMA_FP16(acc[mt][n8], al, bh[n8][0], bh[n8][1]);
                    }
                }
            }

            // pass 2: lo weights (reuse wf regs)
#pragma unroll
            for (int g = 0; g < 4; ++g) wf[g] = __ldg(wbase + fb + (g + 4) * 32);
#pragma unroll
            for (int ks = 0; ks < 2; ++ks) {
                uint32_t bl[4][2];
                uint4 p0 = wf[ks * 2], p1 = wf[ks * 2 + 1];
                bl[0][0] = p0.x; bl[0][1] = p0.y; bl[1][0] = p0.z; bl[1][1] = p0.w;
                bl[2][0] = p1.x; bl[2][1] = p1.y; bl[3][0] = p1.z; bl[3][1] = p1.w;
#pragma unroll
                for (int mt = 0; mt < 2; ++mt)
#pragma unroll
                    for (int n8 = 0; n8 < 4; ++n8)
                        MMA_FP16(acc[mt][n8], ah[ks][mt], bl[n8][0], bl[n8][1]);
            }
        }

        // --- layer boundary: bias + gelu, hi fp16 -> other buffer ----------
#pragma unroll
        for (int mt = 0; mt < 2; ++mt)
#pragma unroll
            for (int n8 = 0; n8 < 4; ++n8) {
                int row = mt * 16 + r_l;
                int col = warp * 32 + n8 * 8 + c_l;
                float* a4 = acc[mt][n8];
                float b0 = bias[col];
                float b1v = bias[col + 1];
                float g0 = gelu_f(a4[0] + b0);
                float g1 = gelu_f(a4[1] + b1v);
                float g2 = gelu_f(a4[2] + b0);
                float g3 = gelu_f(a4[3] + b1v);
                __half2 h01 = __floats2half2_rn(g0, g1);
                __half2 h23 = __floats2half2_rn(g2, g3);
                *reinterpret_cast<uint32_t*>(wrp + row * 528 + col * 2) =
                    *reinterpret_cast<uint32_t*>(&h01);
                *reinterpret_cast<uint32_t*>(wrp + (row + 8) * 528 + col * 2) =
                    *reinterpret_cast<uint32_t*>(&h23);
                a4[0] = a4[1] = a4[2] = a4[3] = 0.0f;
            }
        __syncthreads();
    }

    // --- final layer: 256 -> 9 (hi from ACT0) + symmetrize + R@x@F^T -------
    for (int i = tid; i < 2304; i += 256)
        reinterpret_cast<float*>(smem + W5S)[i] = W5[i];
    if (tid < 9)
        reinterpret_cast<float*>(smem + B5S)[tid] = b5[tid];
    __syncthreads();

#pragma unroll 1
    for (int rr = 0; rr < 4; ++rr) {
        int row = warp * 4 + rr;
        float s[9];
#pragma unroll
        for (int j = 0; j < 9; ++j) s[j] = 0.0f;
#pragma unroll
        for (int t4 = 0; t4 < 4; ++t4) {
            int cp = lane + 32 * t4;
            uint32_t hp = *reinterpret_cast<uint32_t*>(smem + ACT0 + row * 528 + cp * 4);
            __half2 h = *reinterpret_cast<__half2*>(&hp);
            float x0 = __half2float(__low2half(h));
            float x1 = __half2float(__high2half(h));
            const float* w0 = reinterpret_cast<const float*>(smem + W5S) + (2 * cp) * 9;
#pragma unroll
            for (int j = 0; j < 9; ++j) s[j] += x0 * w0[j] + x1 * w0[9 + j];
        }
#pragma unroll
        for (int j = 0; j < 9; ++j) {
#pragma unroll
            for (int o = 16; o >= 1; o >>= 1)
                s[j] += __shfl_xor_sync(0xffffffffu, s[j], o);
        }
        if (lane == 0) {
            int p = tile * 32 + row;
            float x[3][3], xs[3][3], Rm[3][3], Fm[3][3], P[3][3];
#pragma unroll
            for (int i = 0; i < 3; ++i)
#pragma unroll
                for (int j = 0; j < 3; ++j) {
                    x[i][j] = s[i * 3 + j] +
                              reinterpret_cast<float*>(smem + B5S)[i * 3 + j];
                    Rm[i][j] = reinterpret_cast<float*>(smem + RBUF)[row * 9 + i * 3 + j];
                    Fm[i][j] = F[(size_t)p * 9 + i * 3 + j];
                }
#pragma unroll
            for (int i = 0; i < 3; ++i)
#pragma unroll
                for (int j = 0; j < 3; ++j) xs[i][j] = 0.5f * (x[i][j] + x[j][i]);
#pragma unroll
            for (int i = 0; i < 3; ++i)
#pragma unroll
                for (int j = 0; j < 3; ++j)
                    P[i][j] = Rm[i][0] * xs[0][j] + Rm[i][1] * xs[1][j] + Rm[i][2] * xs[2][j];
#pragma unroll
            for (int i = 0; i < 3; ++i)
#pragma unroll
                for (int j = 0; j < 3; ++j)
                    out[(size_t)p * 9 + i * 3 + j] =
                        P[i][0] * Fm[j][0] + P[i][1] * Fm[j][1] + P[i][2] * Fm[j][2];
        }
    }
}

// ---------------------------------------------------------------------------
extern "C" void kernel_launch(void* const* d_in, const int* in_sizes, int n_in,
                              void* d_out, int out_size) {
    const float* F    = (const float*)d_in[0];
    const float* C    = (const float*)d_in[1];
    const float* emb  = (const float*)d_in[2];
    const int*   traj = (const int*)d_in[3];
    const float* W1   = (const float*)d_in[4];
    const float* b1   = (const float*)d_in[5];
    const float* W2   = (const float*)d_in[6];
    const float* b2   = (const float*)d_in[7];
    const float* W3   = (const float*)d_in[8];
    const float* b3   = (const float*)d_in[9];
    const float* W4   = (const float*)d_in[10];
    const float* b4   = (const float*)d_in[11];
    const float* W5   = (const float*)d_in[12];
    const float* b5   = (const float*)d_in[13];
    float* out = (float*)d_out;

    int B = in_sizes[0] / 9;
    if (B > MAXB) B = MAXB;

    static bool attr_set = false;
    if (!attr_set) {
        cudaFuncSetAttribute(fused_kernel,
                             cudaFuncAttributeMaxDynamicSharedMemorySize, SMEM_TOT);
        attr_set = true;
    }

    prep_all_kernel<<<833, 256>>>(emb, traj, W1, b1, W2, W3, W4);
    fused_kernel<<<B / 32, 256, SMEM_TOT>>>(F, C, b2, b3, b4, W5, b5, out);
}

// round 16
// speedup vs baseline: 1.0296x; 1.0296x over previous
#include <cuda_runtime.h>
#include <cuda_fp16.h>
#include <math.h>
#include <math_constants.h>
#include <stdint.h>

// ============================================================================
// StressNNEval — round 15: R13 + cross-chunk weight prefetch.
//   Chunk restructured as hi-pass then lo-pass: wfl LDG covered by hi-pass,
//   wfh(ch+1) double-buffered during current chunk. Peak regs ~126.
//   fp16 split; L1 3-term, L2..L4 2-term; ping-pong hi-act buffers.
// ============================================================================

#define MAXB 262144
#define HID  256

__device__ __align__(128) float    g_b1p[HID];
__device__ __align__(128) uint32_t g_f1[16384];        // L1 frags (hi+lo fp16)
__device__ __align__(128) uint32_t g_fN[3 * 65536];    // L2..L4 frags (hi+lo fp16)

// ---- smem layout (dynamic, 79168 B; 2 CTAs/SM) -----------------------------
#define ACT0     0              // 64 rows x 528B (hi acts, ping; L4 hi at end)
#define ACT1     33792          // 64 rows x 528B (hi acts, pong)
#define X0LO     67584          // 64 rows x 80B (X0 lo)        [dead after L1]
#define BIASALL  72704          // 4 x 256 fp32 (b1p,b2,b3,b4)  [dead after L4]
#define W5S      67584          // overlay: 256x9 fp32          [after mainloop]
#define RBUF     76800          // 64 x 9 fp32                  [persistent]
#define B5S      79104          // 9 fp32
#define SMEM_TOT 79168

// ---------------------------------------------------------------------------
__device__ __forceinline__ uint32_t smem_u32(const void* p) {
    uint32_t a;
    asm("{ .reg .u64 t; cvta.to.shared.u64 t, %1; cvt.u32.u64 %0, t; }"
        : "=r"(a) : "l"(p));
    return a;
}
#define LDSM4(r, addr)                                                        \
    asm volatile("ldmatrix.sync.aligned.m8n8.x4.shared.b16 {%0,%1,%2,%3}, [%4];" \
        : "=r"((r)[0]), "=r"((r)[1]), "=r"((r)[2]), "=r"((r)[3]) : "r"(addr))

#define MMA_FP16(c, a, b0, b1)                                                \
    asm volatile("mma.sync.aligned.m16n8k16.row.col.f32.f16.f16.f32 "         \
        "{%0,%1,%2,%3}, {%4,%5,%6,%7}, {%8,%9}, {%0,%1,%2,%3};"               \
        : "+f"((c)[0]), "+f"((c)[1]), "+f"((c)[2]), "+f"((c)[3])              \
        : "r"((a)[0]), "r"((a)[1]), "r"((a)[2]), "r"((a)[3]),                 \
          "r"(b0), "r"(b1))

__device__ __forceinline__ float gelu_f(float t) {
    return 0.5f * t * (1.0f + erff(t * 0.7071067811865475f));
}

// ---------------------------------------------------------------------------
// prep: block 0 folds latent into b1; blocks 1..64: L1 frags;
//       blocks 65..832: L2..L4 frags.  (fragment layout as rounds 7-14)
// ---------------------------------------------------------------------------
__global__ void prep_all_kernel(const float* __restrict__ emb,
                                const int* __restrict__ traj,
                                const float* __restrict__ W1,
                                const float* __restrict__ b1,
                                const float* __restrict__ W2,
                                const float* __restrict__ W3,
                                const float* __restrict__ W4) {
    int bid = blockIdx.x, tid = threadIdx.x;
    if (bid == 0) {
        int t = traj[0];
        const float* e = emb + (size_t)t * 128;
        float s = b1[tid];
#pragma unroll 4
        for (int k = 0; k < 128; ++k)
            s += e[k] * W1[(size_t)(25 + k) * HID + tid];
        g_b1p[tid] = s;
        return;
    }
    bool isL1 = (bid <= 64);
    int idx = isL1 ? (bid - 1) * 256 + tid : 0;
    int L = 0;
    if (!isL1) {
        int q = (bid - 65) * 256 + tid;
        L = q >> 16;
        idx = q & 65535;
    }
    int lane4 = idx & 3;
    int lane  = (idx >> 2) & 31;
    int g     = (idx >> 7) & 7;
    int warp  = (idx >> 10) & 7;
    int c     = isL1 ? 0 : ((idx >> 13) & 7);
    int half  = g >> 2;
    int ks    = (g >> 1) & 1;
    int npair = g & 1;
    int n8    = npair * 2 + (lane4 >> 1);
    int r     = lane4 & 1;
    int n = warp * 32 + n8 * 8 + (lane >> 2);
    int k = c * 32 + ks * 16 + (lane & 3) * 2 + r * 8;

    float w0, w1;
    if (isL1) {
        w0 = (k < 25)     ? W1[(size_t)k * HID + n]       : 0.0f;
        w1 = (k + 1 < 25) ? W1[(size_t)(k + 1) * HID + n] : 0.0f;
    } else {
        const float* W = (L == 0) ? W2 : ((L == 1) ? W3 : W4);
        w0 = W[(size_t)k * HID + n];
        w1 = W[(size_t)(k + 1) * HID + n];
    }
    __half h0 = __float2half_rn(w0);
    __half h1 = __float2half_rn(w1);
    uint32_t val;
    if (half == 0) {
        val = (uint32_t)*reinterpret_cast<uint16_t*>(&h0) |
              ((uint32_t)*reinterpret_cast<uint16_t*>(&h1) << 16);
    } else {
        __half l0 = __float2half_rn(w0 - __half2float(h0));
        __half l1 = __float2half_rn(w1 - __half2float(h1));
        val = (uint32_t)*reinterpret_cast<uint16_t*>(&l0) |
              ((uint32_t)*reinterpret_cast<uint16_t*>(&l1) << 16);
    }
    if (isL1) g_f1[idx] = val;
    else      g_fN[(size_t)L * 65536 + idx] = val;
}

// ---------------------------------------------------------------------------
// Fused kernel: one CTA per 64-row tile, 256 threads, warp tile 64M x 32N.
// ---------------------------------------------------------------------------
__global__ __launch_bounds__(256, 2)
void fused_kernel(const float* __restrict__ F, const float* __restrict__ C,
                  const float* __restrict__ b2, const float* __restrict__ b3,
                  const float* __restrict__ b4, const float* __restrict__ W5,
                  const float* __restrict__ b5, float* __restrict__ out) {
    extern __shared__ char smem[];
    const uint32_t sb = smem_u32(smem);
    const int tid = threadIdx.x, lane = tid & 31, warp = tid >> 5;
    const int tile = blockIdx.x;

    // stage ALL biases once (read-only afterwards)
    {
        float* ba = reinterpret_cast<float*>(smem + BIASALL);
        ba[tid]       = g_b1p[tid];
        ba[256 + tid] = b2[tid];
        ba[512 + tid] = b3[tid];
        ba[768 + tid] = b4[tid];
    }

    // --- in-kernel prep: invariants + polar rotation -> X0 (hi->ACT0,
    //     lo->X0LO), R -> RBUF
    if (tid < 64) {
        int p = tile * 64 + tid;
        float Fm[3][3];
#pragma unroll
        for (int i = 0; i < 3; ++i)
#pragma unroll
            for (int j = 0; j < 3; ++j)
                Fm[i][j] = F[(size_t)p * 9 + i * 3 + j];

        float G[3][3];
#pragma unroll
        for (int i = 0; i < 3; ++i)
#pragma unroll
            for (int j = 0; j < 3; ++j)
                G[i][j] = Fm[0][i] * Fm[0][j] + Fm[1][i] * Fm[1][j] + Fm[2][i] * Fm[2][j];

        float q = (G[0][0] + G[1][1] + G[2][2]) * (1.0f / 3.0f);
        float p1 = G[0][1] * G[0][1] + G[0][2] * G[0][2] + G[1][2] * G[1][2];
        float p2 = (G[0][0] - q) * (G[0][0] - q) + (G[1][1] - q) * (G[1][1] - q) +
                   (G[2][2] - q) * (G[2][2] - q) + 2.0f * p1;
        float e1, e2, e3;
        float pp = sqrtf(p2 * (1.0f / 6.0f));
        if (pp < 1e-20f) {
            e1 = e2 = e3 = q;
        } else {
            float ip = 1.0f / pp;
            float b00 = (G[0][0] - q) * ip, b11 = (G[1][1] - q) * ip, b22 = (G[2][2] - q) * ip;
            float b01 = G[0][1] * ip, b02 = G[0][2] * ip, b12 = G[1][2] * ip;
            float detB = b00 * (b11 * b22 - b12 * b12) - b01 * (b01 * b22 - b12 * b02) +
                         b02 * (b01 * b12 - b11 * b02);
            float r = fminf(1.0f, fmaxf(-1.0f, detB * 0.5f));
            float phi = acosf(r) * (1.0f / 3.0f);
            e1 = q + 2.0f * pp * cosf(phi);
            e3 = q + 2.0f * pp * cosf(phi + 2.0943951023931953f);
            e2 = 3.0f * q - e1 - e3;
        }
        float s1 = sqrtf(fmaxf(e1, 0.0f));
        float s2 = sqrtf(fmaxf(e2, 0.0f));
        float s3 = sqrtf(fmaxf(e3, 0.0f));

        float detF = Fm[0][0] * (Fm[1][1] * Fm[2][2] - Fm[1][2] * Fm[2][1]) -
                     Fm[0][1] * (Fm[1][0] * Fm[2][2] - Fm[1][2] * Fm[2][0]) +
                     Fm[0][2] * (Fm[1][0] * Fm[2][1] - Fm[1][1] * Fm[2][0]);

        float X[3][3];
#pragma unroll
        for (int i = 0; i < 3; ++i)
#pragma unroll
            for (int j = 0; j < 3; ++j) X[i][j] = Fm[i][j];
#pragma unroll
        for (int it = 0; it < 8; ++it) {
            float c00 = X[1][1] * X[2][2] - X[1][2] * X[2][1];
            float c01 = X[1][2] * X[2][0] - X[1][0] * X[2][2];
            float c02 = X[1][0] * X[2][1] - X[1][1] * X[2][0];
            float c10 = X[0][2] * X[2][1] - X[0][1] * X[2][2];
            float c11 = X[0][0] * X[2][2] - X[0][2] * X[2][0];
            float c12 = X[0][1] * X[2][0] - X[0][0] * X[2][1];
            float c20 = X[0][1] * X[1][2] - X[0][2] * X[1][1];
            float c21 = X[0][2] * X[1][0] - X[0][0] * X[1][2];
            float c22 = X[0][0] * X[1][1] - X[0][1] * X[1][0];
            float d = X[0][0] * c00 + X[0][1] * c01 + X[0][2] * c02;
            float id = 0.5f / d;
            X[0][0] = 0.5f * X[0][0] + id * c00;  X[0][1] = 0.5f * X[0][1] + id * c01;
            X[0][2] = 0.5f * X[0][2] + id * c02;  X[1][0] = 0.5f * X[1][0] + id * c10;
            X[1][1] = 0.5f * X[1][1] + id * c11;  X[1][2] = 0.5f * X[1][2] + id * c12;
            X[2][0] = 0.5f * X[2][0] + id * c20;  X[2][1] = 0.5f * X[2][1] + id * c21;
            X[2][2] = 0.5f * X[2][2] + id * c22;
        }
#pragma unroll
        for (int i = 0; i < 9; ++i)
            reinterpret_cast<float*>(smem + RBUF)[tid * 9 + i] = X[i / 3][i % 3];

        float x0[32];
        x0[0] = s1 - 1.0f;  x0[1] = s2 - 1.0f;  x0[2] = s3 - 1.0f;
#pragma unroll
        for (int i = 0; i < 3; ++i)
#pragma unroll
            for (int j = 0; j < 3; ++j)
                x0[3 + i * 3 + j] = G[i][j] - ((i == j) ? 1.0f : 0.0f);
        x0[12] = detF - 1.0f;
        x0[13] = logf(detF) - 1.0f;
        float f00 = fmaxf(Fm[0][0], 1e-6f);
        x0[14] = f00 - 1.0f;
        x0[15] = logf(f00) - 1.0f;
#pragma unroll
        for (int k = 0; k < 9; ++k) x0[16 + k] = C[(size_t)p * 9 + k];
#pragma unroll
        for (int k = 25; k < 32; ++k) x0[k] = 0.0f;

#pragma unroll
        for (int cp = 0; cp < 16; ++cp) {
            float v0 = x0[2 * cp], v1 = x0[2 * cp + 1];
            __half2 h = __floats2half2_rn(v0, v1);
            float l0 = v0 - __half2float(__low2half(h));
            float l1 = v1 - __half2float(__high2half(h));
            __half2 lo = __floats2half2_rn(l0, l1);
            *reinterpret_cast<uint32_t*>(smem + ACT0 + tid * 528 + cp * 4) =
                *reinterpret_cast<uint32_t*>(&h);
            *reinterpret_cast<uint32_t*>(smem + X0LO + tid * 80 + cp * 4) =
                *reinterpret_cast<uint32_t*>(&lo);
        }
    }
    __syncthreads();

    // --- mainloop over layers; chunks inside; ping-pong act buffers --------
    float acc[4][4][4];
#pragma unroll
    for (int mt = 0; mt < 4; ++mt)
#pragma unroll
        for (int n8 = 0; n8 < 4; ++n8)
#pragma unroll
            for (int r = 0; r < 4; ++r) acc[mt][n8][r] = 0.0f;

    const uint32_t a_off    = (uint32_t)(lane & 15) * 528u + ((lane >> 4) << 4);
    const uint32_t a_off_lo = (uint32_t)(lane & 15) * 80u  + ((lane >> 4) << 4);
    const int r_l = lane >> 2, c_l = (lane & 3) << 1;

#pragma unroll 1
    for (int l = 0; l < 4; ++l) {
        const int nch = (l == 0) ? 1 : 8;
        const uint32_t rd = sb + ((l & 1) ? ACT1 : ACT0);   // LDSM only
        char* wrp = smem + ((l & 1) ? ACT0 : ACT1);         // l=3 -> ACT0
        const uint4* wbase = (l == 0)
            ? reinterpret_cast<const uint4*>(g_f1)
            : reinterpret_cast<const uint4*>(g_fN + (size_t)(l - 1) * 65536);
        const float* bias = reinterpret_cast<const float*>(smem + BIASALL) + l * 256;

        uint4 wfhA[4], wfhB[4], wfl[4];
        // preload chunk-0 hi fragments
        {
            const int fb = (warp * 8) * 32 + lane;
#pragma unroll
            for (int g = 0; g < 4; ++g) wfhA[g] = __ldg(wbase + fb + g * 32);
        }

        // one chunk: hi-pass (wfhc) then lo-pass (wfl); prefetch next hi
        auto process = [&](int ch, const uint4* wfhc, uint4* wfhn, bool pre) {
            const int fb = ((ch * 8 + warp) * 8) * 32 + lane;
#pragma unroll
            for (int g = 0; g < 4; ++g) wfl[g] = __ldg(wbase + fb + (g + 4) * 32);
            if (pre) {
                const int fb2 = (((ch + 1) * 8 + warp) * 8) * 32 + lane;
#pragma unroll
                for (int g = 0; g < 4; ++g) wfhn[g] = __ldg(wbase + fb2 + g * 32);
            }
            const uint32_t acol = (uint32_t)ch * 64u;
            // hi-pass
#pragma unroll
            for (int ks = 0; ks < 2; ++ks) {
                uint32_t bh[4][2];
                uint4 q0 = wfhc[ks * 2], q1 = wfhc[ks * 2 + 1];
                bh[0][0] = q0.x; bh[0][1] = q0.y; bh[1][0] = q0.z; bh[1][1] = q0.w;
                bh[2][0] = q1.x; bh[2][1] = q1.y; bh[3][0] = q1.z; bh[3][1] = q1.w;
#pragma unroll
                for (int mt = 0; mt < 4; ++mt) {
                    uint32_t ah[4];
                    LDSM4(ah, rd + a_off + mt * 8448 + acol + ks * 32);
#pragma unroll
                    for (int n8 = 0; n8 < 4; ++n8)
                        MMA_FP16(acc[mt][n8], ah, bh[n8][0], bh[n8][1]);
                    if (l == 0) {
                        uint32_t al[4];
                        LDSM4(al, sb + X0LO + a_off_lo + mt * 1280 + ks * 32);
#pragma unroll
                        for (int n8 = 0; n8 < 4; ++n8)
                            MMA_FP16(acc[mt][n8], al, bh[n8][0], bh[n8][1]);
                    }
                }
            }
            // lo-pass (A-fragments re-LDSM'd; wfl has arrived by now)
#pragma unroll
            for (int ks = 0; ks < 2; ++ks) {
                uint32_t bl[4][2];
                uint4 p0 = wfl[ks * 2], p1 = wfl[ks * 2 + 1];
                bl[0][0] = p0.x; bl[0][1] = p0.y; bl[1][0] = p0.z; bl[1][1] = p0.w;
                bl[2][0] = p1.x; bl[2][1] = p1.y; bl[3][0] = p1.z; bl[3][1] = p1.w;
#pragma unroll
                for (int mt = 0; mt < 4; ++mt) {
                    uint32_t ah[4];
                    LDSM4(ah, rd + a_off + mt * 8448 + acol + ks * 32);
#pragma unroll
                    for (int n8 = 0; n8 < 4; ++n8)
                        MMA_FP16(acc[mt][n8], ah, bl[n8][0], bl[n8][1]);
                }
            }
        };

#pragma unroll 1
        for (int ch = 0; ch < nch; ch += 2) {
            process(ch, wfhA, wfhB, ch + 1 < nch);
            if (ch + 1 < nch)
                process(ch + 1, wfhB, wfhA, ch + 2 < nch);
        }

        // --- layer boundary: bias + gelu, hi fp16 -> other buffer ----------
#pragma unroll
        for (int mt = 0; mt < 4; ++mt)
#pragma unroll
            for (int n8 = 0; n8 < 4; ++n8) {
                int row = mt * 16 + r_l;
                int col = warp * 32 + n8 * 8 + c_l;
                float* a4 = acc[mt][n8];
                float b0 = bias[col];
                float b1v = bias[col + 1];
                float g0 = gelu_f(a4[0] + b0);
                float g1 = gelu_f(a4[1] + b1v);
                float g2 = gelu_f(a4[2] + b0);
                float g3 = gelu_f(a4[3] + b1v);
                __half2 h01 = __floats2half2_rn(g0, g1);
                __half2 h23 = __floats2half2_rn(g2, g3);
                *reinterpret_cast<uint32_t*>(wrp + row * 528 + col * 2) =
                    *reinterpret_cast<uint32_t*>(&h01);
                *reinterpret_cast<uint32_t*>(wrp + (row + 8) * 528 + col * 2) =
                    *reinterpret_cast<uint32_t*>(&h23);
                a4[0] = a4[1] = a4[2] = a4[3] = 0.0f;
            }
        __syncthreads();
    }

    // --- final layer: 256 -> 9 (hi from ACT0) + symmetrize + R@x@F^T -------
    for (int i = tid; i < 2304; i += 256)
        reinterpret_cast<float*>(smem + W5S)[i] = W5[i];
    if (tid < 9)
        reinterpret_cast<float*>(smem + B5S)[tid] = b5[tid];
    __syncthreads();

#pragma unroll 1
    for (int rr = 0; rr < 8; ++rr) {
        int row = warp * 8 + rr;
        float s[9];
#pragma unroll
        for (int j = 0; j < 9; ++j) s[j] = 0.0f;
#pragma unroll
        for (int t4 = 0; t4 < 4; ++t4) {
            int cp = lane + 32 * t4;
            uint32_t hp = *reinterpret_cast<uint32_t*>(smem + ACT0 + row * 528 + cp * 4);
            __half2 h = *reinterpret_cast<__half2*>(&hp);
            float x0 = __half2float(__low2half(h));
            float x1 = __half2float(__high2half(h));
            const float* w0 = reinterpret_cast<const float*>(smem + W5S) + (2 * cp) * 9;
#pragma unroll
            for (int j = 0; j < 9; ++j) s[j] += x0 * w0[j] + x1 * w0[9 + j];
        }
#pragma unroll
        for (int j = 0; j < 9; ++j) {
#pragma unroll
            for (int o = 16; o >= 1; o >>= 1)
                s[j] += __shfl_xor_sync(0xffffffffu, s[j], o);
        }
        if (lane == 0) {
            int p = tile * 64 + row;
            float x[3][3], xs[3][3], Rm[3][3], Fm[3][3], P[3][3];
#pragma unroll
            for (int i = 0; i < 3; ++i)
#pragma unroll
                for (int j = 0; j < 3; ++j) {
                    x[i][j] = s[i * 3 + j] +
                              reinterpret_cast<float*>(smem + B5S)[i * 3 + j];
                    Rm[i][j] = reinterpret_cast<float*>(smem + RBUF)[row * 9 + i * 3 + j];
                    Fm[i][j] = F[(size_t)p * 9 + i * 3 + j];
                }
#pragma unroll
            for (int i = 0; i < 3; ++i)
#pragma unroll
                for (int j = 0; j < 3; ++j) xs[i][j] = 0.5f * (x[i][j] + x[j][i]);
#pragma unroll
            for (int i = 0; i < 3; ++i)
#pragma unroll
                for (int j = 0; j < 3; ++j)
                    P[i][j] = Rm[i][0] * xs[0][j] + Rm[i][1] * xs[1][j] + Rm[i][2] * xs[2][j];
#pragma unroll
            for (int i = 0; i < 3; ++i)
#pragma unroll
                for (int j = 0; j < 3; ++j)
                    out[(size_t)p * 9 + i * 3 + j] =
                        P[i][0] * Fm[j][0] + P[i][1] * Fm[j][1] + P[i][2] * Fm[j][2];
        }
    }
}

// ---------------------------------------------------------------------------
extern "C" void kernel_launch(void* const* d_in, const int* in_sizes, int n_in,
                              void* d_out, int out_size) {
    const float* F    = (const float*)d_in[0];
    const float* C    = (const float*)d_in[1];
    const float* emb  = (const float*)d_in[2];
    const int*   traj = (const int*)d_in[3];
    const float* W1   = (const float*)d_in[4];
    const float* b1   = (const float*)d_in[5];
    const float* W2   = (const float*)d_in[6];
    const float* b2   = (const float*)d_in[7];
    const float* W3   = (const float*)d_in[8];
    const float* b3   = (const float*)d_in[9];
    const float* W4   = (const float*)d_in[10];
    const float* b4   = (const float*)d_in[11];
    const float* W5   = (const float*)d_in[12];
    const float* b5   = (const float*)d_in[13];
    float* out = (float*)d_out;

    int B = in_sizes[0] / 9;
    if (B > MAXB) B = MAXB;

    static bool attr_set = false;
    if (!attr_set) {
        cudaFuncSetAttribute(fused_kernel,
                             cudaFuncAttributeMaxDynamicSharedMemorySize, SMEM_TOT);
        attr_set = true;
    }

    prep_all_kernel<<<833, 256>>>(emb, traj, W1, b1, W2, W3, W4);
    fused_kernel<<<B / 64, 256, SMEM_TOT>>>(F, C, b2, b3, b4, W5, b5, out);
}

// round 17
// speedup vs baseline: 1.4389x; 1.3976x over previous
#include <cuda_runtime.h>
#include <cuda_fp16.h>
#include <math.h>
#include <math_constants.h>
#include <stdint.h>

// ============================================================================
// StressNNEval — round 17: R13 base + drop weight-lo terms on L2..L4.
//   Error model (calibrated 2.70e-4/event, 4 validated hits): 7 events ->
//   predicted rel_err 7.15e-4 (< 1e-3, margin 1.4x).
//   mma units 51 -> 27; weight LDG halves on interior layers.
//   L1 keeps full 3-term (X0 and W1 exact). fp16 throughout.
// ============================================================================

#define MAXB 262144
#define HID  256

__device__ __align__(128) float    g_b1p[HID];
__device__ __align__(128) uint32_t g_f1[16384];        // L1 frags (hi+lo fp16)
__device__ __align__(128) uint32_t g_fN[3 * 65536];    // L2..L4 frags (hi used)

// ---- smem layout (dynamic, 79168 B; 2 CTAs/SM) -----------------------------
#define ACT0     0              // 64 rows x 528B (hi acts, ping; L4 hi at end)
#define ACT1     33792          // 64 rows x 528B (hi acts, pong)
#define X0LO     67584          // 64 rows x 80B (X0 lo)        [dead after L1]
#define BIASALL  72704          // 4 x 256 fp32 (b1p,b2,b3,b4)  [dead after L4]
#define W5S      67584          // overlay: 256x9 fp32          [after mainloop]
#define RBUF     76800          // 64 x 9 fp32                  [persistent]
#define B5S      79104          // 9 fp32
#define SMEM_TOT 79168

// ---------------------------------------------------------------------------
__device__ __forceinline__ uint32_t smem_u32(const void* p) {
    uint32_t a;
    asm("{ .reg .u64 t; cvta.to.shared.u64 t, %1; cvt.u32.u64 %0, t; }"
        : "=r"(a) : "l"(p));
    return a;
}
#define LDSM4(r, addr)                                                        \
    asm volatile("ldmatrix.sync.aligned.m8n8.x4.shared.b16 {%0,%1,%2,%3}, [%4];" \
        : "=r"((r)[0]), "=r"((r)[1]), "=r"((r)[2]), "=r"((r)[3]) : "r"(addr))

#define MMA_FP16(c, a, b0, b1)                                                \
    asm volatile("mma.sync.aligned.m16n8k16.row.col.f32.f16.f16.f32 "         \
        "{%0,%1,%2,%3}, {%4,%5,%6,%7}, {%8,%9}, {%0,%1,%2,%3};"               \
        : "+f"((c)[0]), "+f"((c)[1]), "+f"((c)[2]), "+f"((c)[3])              \
        : "r"((a)[0]), "r"((a)[1]), "r"((a)[2]), "r"((a)[3]),                 \
          "r"(b0), "r"(b1))

__device__ __forceinline__ float gelu_f(float t) {
    return 0.5f * t * (1.0f + erff(t * 0.7071067811865475f));
}

// ---------------------------------------------------------------------------
// prep: block 0 folds latent into b1; blocks 1..64: L1 frags;
//       blocks 65..832: L2..L4 frags.  (fragment layout as rounds 7-16;
//       lo halves still produced for L2..L4 but unused by the mainloop)
// ---------------------------------------------------------------------------
__global__ void prep_all_kernel(const float* __restrict__ emb,
                                const int* __restrict__ traj,
                                const float* __restrict__ W1,
                                const float* __restrict__ b1,
                                const float* __restrict__ W2,
                                const float* __restrict__ W3,
                                const float* __restrict__ W4) {
    int bid = blockIdx.x, tid = threadIdx.x;
    if (bid == 0) {
        int t = traj[0];
        const float* e = emb + (size_t)t * 128;
        float s = b1[tid];
#pragma unroll 4
        for (int k = 0; k < 128; ++k)
            s += e[k] * W1[(size_t)(25 + k) * HID + tid];
        g_b1p[tid] = s;
        return;
    }
    bool isL1 = (bid <= 64);
    int idx = isL1 ? (bid - 1) * 256 + tid : 0;
    int L = 0;
    if (!isL1) {
        int q = (bid - 65) * 256 + tid;
        L = q >> 16;
        idx = q & 65535;
    }
    int lane4 = idx & 3;
    int lane  = (idx >> 2) & 31;
    int g     = (idx >> 7) & 7;
    int warp  = (idx >> 10) & 7;
    int c     = isL1 ? 0 : ((idx >> 13) & 7);
    int half  = g >> 2;
    int ks    = (g >> 1) & 1;
    int npair = g & 1;
    int n8    = npair * 2 + (lane4 >> 1);
    int r     = lane4 & 1;
    int n = warp * 32 + n8 * 8 + (lane >> 2);
    int k = c * 32 + ks * 16 + (lane & 3) * 2 + r * 8;

    float w0, w1;
    if (isL1) {
        w0 = (k < 25)     ? W1[(size_t)k * HID + n]       : 0.0f;
        w1 = (k + 1 < 25) ? W1[(size_t)(k + 1) * HID + n] : 0.0f;
    } else {
        const float* W = (L == 0) ? W2 : ((L == 1) ? W3 : W4);
        w0 = W[(size_t)k * HID + n];
        w1 = W[(size_t)(k + 1) * HID + n];
    }
    __half h0 = __float2half_rn(w0);
    __half h1 = __float2half_rn(w1);
    uint32_t val;
    if (half == 0) {
        val = (uint32_t)*reinterpret_cast<uint16_t*>(&h0) |
              ((uint32_t)*reinterpret_cast<uint16_t*>(&h1) << 16);
    } else {
        __half l0 = __float2half_rn(w0 - __half2float(h0));
        __half l1 = __float2half_rn(w1 - __half2float(h1));
        val = (uint32_t)*reinterpret_cast<uint16_t*>(&l0) |
              ((uint32_t)*reinterpret_cast<uint16_t*>(&l1) << 16);
    }
    if (isL1) g_f1[idx] = val;
    else      g_fN[(size_t)L * 65536 + idx] = val;
}

// ---------------------------------------------------------------------------
// Fused kernel: one CTA per 64-row tile, 256 threads, warp tile 64M x 32N.
// ---------------------------------------------------------------------------
__global__ __launch_bounds__(256, 2)
void fused_kernel(const float* __restrict__ F, const float* __restrict__ C,
                  const float* __restrict__ b2, const float* __restrict__ b3,
                  const float* __restrict__ b4, const float* __restrict__ W5,
                  const float* __restrict__ b5, float* __restrict__ out) {
    extern __shared__ char smem[];
    const uint32_t sb = smem_u32(smem);
    const int tid = threadIdx.x, lane = tid & 31, warp = tid >> 5;
    const int tile = blockIdx.x;

    // stage ALL biases once (read-only afterwards)
    {
        float* ba = reinterpret_cast<float*>(smem + BIASALL);
        ba[tid]       = g_b1p[tid];
        ba[256 + tid] = b2[tid];
        ba[512 + tid] = b3[tid];
        ba[768 + tid] = b4[tid];
    }

    // --- in-kernel prep: invariants + polar rotation -> X0 (hi->ACT0,
    //     lo->X0LO), R -> RBUF
    if (tid < 64) {
        int p = tile * 64 + tid;
        float Fm[3][3];
#pragma unroll
        for (int i = 0; i < 3; ++i)
#pragma unroll
            for (int j = 0; j < 3; ++j)
                Fm[i][j] = F[(size_t)p * 9 + i * 3 + j];

        float G[3][3];
#pragma unroll
        for (int i = 0; i < 3; ++i)
#pragma unroll
            for (int j = 0; j < 3; ++j)
                G[i][j] = Fm[0][i] * Fm[0][j] + Fm[1][i] * Fm[1][j] + Fm[2][i] * Fm[2][j];

        float q = (G[0][0] + G[1][1] + G[2][2]) * (1.0f / 3.0f);
        float p1 = G[0][1] * G[0][1] + G[0][2] * G[0][2] + G[1][2] * G[1][2];
        float p2 = (G[0][0] - q) * (G[0][0] - q) + (G[1][1] - q) * (G[1][1] - q) +
                   (G[2][2] - q) * (G[2][2] - q) + 2.0f * p1;
        float e1, e2, e3;
        float pp = sqrtf(p2 * (1.0f / 6.0f));
        if (pp < 1e-20f) {
            e1 = e2 = e3 = q;
        } else {
            float ip = 1.0f / pp;
            float b00 = (G[0][0] - q) * ip, b11 = (G[1][1] - q) * ip, b22 = (G[2][2] - q) * ip;
            float b01 = G[0][1] * ip, b02 = G[0][2] * ip, b12 = G[1][2] * ip;
            float detB = b00 * (b11 * b22 - b12 * b12) - b01 * (b01 * b22 - b12 * b02) +
                         b02 * (b01 * b12 - b11 * b02);
            float r = fminf(1.0f, fmaxf(-1.0f, detB * 0.5f));
            float phi = acosf(r) * (1.0f / 3.0f);
            e1 = q + 2.0f * pp * cosf(phi);
            e3 = q + 2.0f * pp * cosf(phi + 2.0943951023931953f);
            e2 = 3.0f * q - e1 - e3;
        }
        float s1 = sqrtf(fmaxf(e1, 0.0f));
        float s2 = sqrtf(fmaxf(e2, 0.0f));
        float s3 = sqrtf(fmaxf(e3, 0.0f));

        float detF = Fm[0][0] * (Fm[1][1] * Fm[2][2] - Fm[1][2] * Fm[2][1]) -
                     Fm[0][1] * (Fm[1][0] * Fm[2][2] - Fm[1][2] * Fm[2][0]) +
                     Fm[0][2] * (Fm[1][0] * Fm[2][1] - Fm[1][1] * Fm[2][0]);

        float X[3][3];
#pragma unroll
        for (int i = 0; i < 3; ++i)
#pragma unroll
            for (int j = 0; j < 3; ++j) X[i][j] = Fm[i][j];
#pragma unroll
        for (int it = 0; it < 8; ++it) {
            float c00 = X[1][1] * X[2][2] - X[1][2] * X[2][1];
            float c01 = X[1][2] * X[2][0] - X[1][0] * X[2][2];
            float c02 = X[1][0] * X[2][1] - X[1][1] * X[2][0];
            float c10 = X[0][2] * X[2][1] - X[0][1] * X[2][2];
            float c11 = X[0][0] * X[2][2] - X[0][2] * X[2][0];
            float c12 = X[0][1] * X[2][0] - X[0][0] * X[2][1];
            float c20 = X[0][1] * X[1][2] - X[0][2] * X[1][1];
            float c21 = X[0][2] * X[1][0] - X[0][0] * X[1][2];
            float c22 = X[0][0] * X[1][1] - X[0][1] * X[1][0];
            float d = X[0][0] * c00 + X[0][1] * c01 + X[0][2] * c02;
            float id = 0.5f / d;
            X[0][0] = 0.5f * X[0][0] + id * c00;  X[0][1] = 0.5f * X[0][1] + id * c01;
            X[0][2] = 0.5f * X[0][2] + id * c02;  X[1][0] = 0.5f * X[1][0] + id * c10;
            X[1][1] = 0.5f * X[1][1] + id * c11;  X[1][2] = 0.5f * X[1][2] + id * c12;
            X[2][0] = 0.5f * X[2][0] + id * c20;  X[2][1] = 0.5f * X[2][1] + id * c21;
            X[2][2] = 0.5f * X[2][2] + id * c22;
        }
#pragma unroll
        for (int i = 0; i < 9; ++i)
            reinterpret_cast<float*>(smem + RBUF)[tid * 9 + i] = X[i / 3][i % 3];

        float x0[32];
        x0[0] = s1 - 1.0f;  x0[1] = s2 - 1.0f;  x0[2] = s3 - 1.0f;
#pragma unroll
        for (int i = 0; i < 3; ++i)
#pragma unroll
            for (int j = 0; j < 3; ++j)
                x0[3 + i * 3 + j] = G[i][j] - ((i == j) ? 1.0f : 0.0f);
        x0[12] = detF - 1.0f;
        x0[13] = logf(detF) - 1.0f;
        float f00 = fmaxf(Fm[0][0], 1e-6f);
        x0[14] = f00 - 1.0f;
        x0[15] = logf(f00) - 1.0f;
#pragma unroll
        for (int k = 0; k < 9; ++k) x0[16 + k] = C[(size_t)p * 9 + k];
#pragma unroll
        for (int k = 25; k < 32; ++k) x0[k] = 0.0f;

#pragma unroll
        for (int cp = 0; cp < 16; ++cp) {
            float v0 = x0[2 * cp], v1 = x0[2 * cp + 1];
            __half2 h = __floats2half2_rn(v0, v1);
            float l0 = v0 - __half2float(__low2half(h));
            float l1 = v1 - __half2float(__high2half(h));
            __half2 lo = __floats2half2_rn(l0, l1);
            *reinterpret_cast<uint32_t*>(smem + ACT0 + tid * 528 + cp * 4) =
                *reinterpret_cast<uint32_t*>(&h);
            *reinterpret_cast<uint32_t*>(smem + X0LO + tid * 80 + cp * 4) =
                *reinterpret_cast<uint32_t*>(&lo);
        }
    }
    __syncthreads();

    // --- mainloop over layers; chunks inside; ping-pong act buffers --------
    float acc[4][4][4];
#pragma unroll
    for (int mt = 0; mt < 4; ++mt)
#pragma unroll
        for (int n8 = 0; n8 < 4; ++n8)
#pragma unroll
            for (int r = 0; r < 4; ++r) acc[mt][n8][r] = 0.0f;

    const uint32_t a_off    = (uint32_t)(lane & 15) * 528u + ((lane >> 4) << 4);
    const uint32_t a_off_lo = (uint32_t)(lane & 15) * 80u  + ((lane >> 4) << 4);
    const int r_l = lane >> 2, c_l = (lane & 3) << 1;

#pragma unroll 1
    for (int l = 0; l < 4; ++l) {
        const int nch = (l == 0) ? 1 : 8;
        const uint32_t rd = sb + ((l & 1) ? ACT1 : ACT0);   // LDSM only
        char* wrp = smem + ((l & 1) ? ACT0 : ACT1);         // l=3 -> ACT0
        const uint4* wbase = (l == 0)
            ? reinterpret_cast<const uint4*>(g_f1)
            : reinterpret_cast<const uint4*>(g_fN + (size_t)(l - 1) * 65536);
        const float* bias = reinterpret_cast<const float*>(smem + BIASALL) + l * 256;

#pragma unroll 1
        for (int ch = 0; ch < nch; ++ch) {
            const int fb = ((ch * 8 + warp) * 8) * 32 + lane;
            // hi weight fragments (always); lo only for L1
            uint4 wfh[4];
#pragma unroll
            for (int g = 0; g < 4; ++g)
                wfh[g] = __ldg(wbase + fb + g * 32);
            uint4 wfl[4];
            if (l == 0) {
#pragma unroll
                for (int g = 0; g < 4; ++g)
                    wfl[g] = __ldg(wbase + fb + (g + 4) * 32);
            }
            const uint32_t acol = (uint32_t)ch * 64u;
#pragma unroll
            for (int ks = 0; ks < 2; ++ks) {
                uint32_t bh[4][2];
                {
                    uint4 q0 = wfh[ks * 2], q1 = wfh[ks * 2 + 1];
                    bh[0][0] = q0.x; bh[0][1] = q0.y; bh[1][0] = q0.z; bh[1][1] = q0.w;
                    bh[2][0] = q1.x; bh[2][1] = q1.y; bh[3][0] = q1.z; bh[3][1] = q1.w;
                }
#pragma unroll
                for (int mt = 0; mt < 4; ++mt) {
                    uint32_t ah[4];
                    LDSM4(ah, rd + a_off + mt * 8448 + acol + ks * 32);
#pragma unroll
                    for (int n8 = 0; n8 < 4; ++n8)
                        MMA_FP16(acc[mt][n8], ah, bh[n8][0], bh[n8][1]);
                    if (l == 0) {
                        // act-lo x w-hi
                        uint32_t al[4];
                        LDSM4(al, sb + X0LO + a_off_lo + mt * 1280 + ks * 32);
#pragma unroll
                        for (int n8 = 0; n8 < 4; ++n8)
                            MMA_FP16(acc[mt][n8], al, bh[n8][0], bh[n8][1]);
                        // act-hi x w-lo (W1 exactness)
                        uint32_t bl[4][2];
                        uint4 p0 = wfl[ks * 2], p1 = wfl[ks * 2 + 1];
                        bl[0][0] = p0.x; bl[0][1] = p0.y; bl[1][0] = p0.z; bl[1][1] = p0.w;
                        bl[2][0] = p1.x; bl[2][1] = p1.y; bl[3][0] = p1.z; bl[3][1] = p1.w;
#pragma unroll
                        for (int n8 = 0; n8 < 4; ++n8)
                            MMA_FP16(acc[mt][n8], ah, bl[n8][0], bl[n8][1]);
                    }
                }
            }
        }

        // --- layer boundary: bias + gelu, hi fp16 -> other buffer ----------
#pragma unroll
        for (int mt = 0; mt < 4; ++mt)
#pragma unroll
            for (int n8 = 0; n8 < 4; ++n8) {
                int row = mt * 16 + r_l;
                int col = warp * 32 + n8 * 8 + c_l;
                float* a4 = acc[mt][n8];
                float b0 = bias[col];
                float b1v = bias[col + 1];
                float g0 = gelu_f(a4[0] + b0);
                float g1 = gelu_f(a4[1] + b1v);
                float g2 = gelu_f(a4[2] + b0);
                float g3 = gelu_f(a4[3] + b1v);
                __half2 h01 = __floats2half2_rn(g0, g1);
                __half2 h23 = __floats2half2_rn(g2, g3);
                *reinterpret_cast<uint32_t*>(wrp + row * 528 + col * 2) =
                    *reinterpret_cast<uint32_t*>(&h01);
                *reinterpret_cast<uint32_t*>(wrp + (row + 8) * 528 + col * 2) =
                    *reinterpret_cast<uint32_t*>(&h23);
                a4[0] = a4[1] = a4[2] = a4[3] = 0.0f;
            }
        __syncthreads();
    }

    // --- final layer: 256 -> 9 (hi from ACT0) + symmetrize + R@x@F^T -------
    for (int i = tid; i < 2304; i += 256)
        reinterpret_cast<float*>(smem + W5S)[i] = W5[i];
    if (tid < 9)
        reinterpret_cast<float*>(smem + B5S)[tid] = b5[tid];
    __syncthreads();

#pragma unroll 1
    for (int rr = 0; rr < 8; ++rr) {
        int row = warp * 8 + rr;
        float s[9];
#pragma unroll
        for (int j = 0; j < 9; ++j) s[j] = 0.0f;
#pragma unroll
        for (int t4 = 0; t4 < 4; ++t4) {
            int cp = lane + 32 * t4;
            uint32_t hp = *reinterpret_cast<uint32_t*>(smem + ACT0 + row * 528 + cp * 4);
            __half2 h = *reinterpret_cast<__half2*>(&hp);
            float x0 = __half2float(__low2half(h));
            float x1 = __half2float(__high2half(h));
            const float* w0 = reinterpret_cast<const float*>(smem + W5S) + (2 * cp) * 9;
#pragma unroll
            for (int j = 0; j < 9; ++j) s[j] += x0 * w0[j] + x1 * w0[9 + j];
        }
#pragma unroll
        for (int j = 0; j < 9; ++j) {
#pragma unroll
            for (int o = 16; o >= 1; o >>= 1)
                s[j] += __shfl_xor_sync(0xffffffffu, s[j], o);
        }
        if (lane == 0) {
            int p = tile * 64 + row;
            float x[3][3], xs[3][3], Rm[3][3], Fm[3][3], P[3][3];
#pragma unroll
            for (int i = 0; i < 3; ++i)
#pragma unroll
                for (int j = 0; j < 3; ++j) {
                    x[i][j] = s[i * 3 + j] +
                              reinterpret_cast<float*>(smem + B5S)[i * 3 + j];
                    Rm[i][j] = reinterpret_cast<float*>(smem + RBUF)[row * 9 + i * 3 + j];
                    Fm[i][j] = F[(size_t)p * 9 + i * 3 + j];
                }
#pragma unroll
            for (int i = 0; i < 3; ++i)
#pragma unroll
                for (int j = 0; j < 3; ++j) xs[i][j] = 0.5f * (x[i][j] + x[j][i]);
#pragma unroll
            for (int i = 0; i < 3; ++i)
#pragma unroll
                for (int j = 0; j < 3; ++j)
                    P[i][j] = Rm[i][0] * xs[0][j] + Rm[i][1] * xs[1][j] + Rm[i][2] * xs[2][j];
#pragma unroll
            for (int i = 0; i < 3; ++i)
#pragma unroll
                for (int j = 0; j < 3; ++j)
                    out[(size_t)p * 9 + i * 3 + j] =
                        P[i][0] * Fm[j][0] + P[i][1] * Fm[j][1] + P[i][2] * Fm[j][2];
        }
    }
}

// ---------------------------------------------------------------------------
extern "C" void kernel_launch(void* const* d_in, const int* in_sizes, int n_in,
                              void* d_out, int out_size) {
    const float* F    = (const float*)d_in[0];
    const float* C    = (const float*)d_in[1];
    const float* emb  = (const float*)d_in[2];
    const int*   traj = (const int*)d_in[3];
    const float* W1   = (const float*)d_in[4];
    const float* b1   = (const float*)d_in[5];
    const float* W2   = (const float*)d_in[6];
    const float* b2   = (const float*)d_in[7];
    const float* W3   = (const float*)d_in[8];
    const float* b3   = (const float*)d_in[9];
    const float* W4   = (const float*)d_in[10];
    const float* b4   = (const float*)d_in[11];
    const float* W5   = (const float*)d_in[12];
    const float* b5   = (const float*)d_in[13];
    float* out = (float*)d_out;

    int B = in_sizes[0] / 9;
    if (B > MAXB) B = MAXB;

    static bool attr_set = false;
    if (!attr_set) {
        cudaFuncSetAttribute(fused_kernel,
                             cudaFuncAttributeMaxDynamicSharedMemorySize, SMEM_TOT);
        attr_set = true;
    }

    prep_all_kernel<<<833, 256>>>(emb, traj, W1, b1, W2, W3, W4);
    fused_kernel<<<B / 64, 256, SMEM_TOT>>>(F, C, b2, b3, b4, W5, b5, out);
}